// round 1
// baseline (speedup 1.0000x reference)
#include <cuda_runtime.h>

// Dense_RBS_density_3D: rho_out = W rho W^T where W = U38...U0, each U a
// sparse Givens-rotation layer (38 disjoint 2x2 rotations on the C(40,2)=780
// dim Hamming-weight-2 basis). We exploit sparsity: ~0.9 GFLOP total, HBM-bound.
//
// Kernel K applies column rotations (M -> M U0^T U1^T ... U38^T = M W^T) to a
// tile of contiguous rows held in smem, then writes the tile TRANSPOSED:
//   K(M) = (M W^T)^T = W M^T   =>   K(K(rho)) = W rho W^T   (exact)
// So one kernel, launched twice, with a __device__ scratch buffer between.

#define DD      780       // C(40,2)
#define NGATES  39
#define NPAIRS  38        // rotations per gate
#define NBATCH  64
#define RROWS   65        // rows per tile (780 = 65 * 12)
#define NTILES  12
#define STRIDE  781       // odd padded row stride -> conflict-free smem
#define THREADS 512

__device__ float g_tmp[(size_t)NBATCH * DD * DD];  // 155.7 MB scratch

// lexicographic rank of pair (p,q), p<q, over 40 qubits
__device__ __forceinline__ int pair_rank(int p, int q) {
    return p * 39 - (p * (p - 1)) / 2 + (q - p - 1);
}

__device__ __forceinline__ void rbs_body(const float* __restrict__ in,
                                         float* __restrict__ out,
                                         const float* __restrict__ angles) {
    extern __shared__ float tile[];            // RROWS * STRIDE floats
    __shared__ float   s_cos[NGATES], s_sin[NGATES];
    __shared__ ushort2 s_pairs[NGATES * NPAIRS];

    const int tid = threadIdx.x;
    const int b   = blockIdx.x / NTILES;
    const int t   = blockIdx.x - b * NTILES;
    const int r0  = t * RROWS;

    // angles -> cos/sin
    if (tid < NGATES) {
        float th = angles[tid];
        s_cos[tid] = cosf(th);
        s_sin[tid] = sinf(th);
    }
    // pair tables: gate g = (a, a+1); x runs over qubits != a, a+1
    for (int n = tid; n < NGATES * NPAIRS; n += THREADS) {
        int g = n / NPAIRS;
        int p = n - g * NPAIRS;
        int a = g, bq = g + 1;
        int x = p + (p >= a ? 2 : 0);
        int i = (x < a)  ? pair_rank(x, a)  : pair_rank(a, x);   // state {a, x}
        int j = (x < bq) ? pair_rank(x, bq) : pair_rank(bq, x);  // state {a+1, x}
        s_pairs[n] = make_ushort2((unsigned short)i, (unsigned short)j);
    }

    // load tile: rows r0..r0+64 of batch b, coalesced float4
    const float* src = in + (size_t)b * DD * DD + (size_t)r0 * DD;
    for (int n = tid; n < RROWS * (DD / 4); n += THREADS) {
        int row = n / (DD / 4);
        int c4  = n - row * (DD / 4);
        float4 v = __ldg((const float4*)(src + (size_t)row * DD) + c4);
        float* d = &tile[row * STRIDE + c4 * 4];
        d[0] = v.x; d[1] = v.y; d[2] = v.z; d[3] = v.w;
    }
    __syncthreads();

    // sequential gates; within a gate all 38 pairs are disjoint -> parallel
    for (int g = 0; g < NGATES; g++) {
        const float c = s_cos[g], s = s_sin[g];
        const ushort2* gp = &s_pairs[g * NPAIRS];
        for (int n = tid; n < NPAIRS * RROWS; n += THREADS) {
            int p   = n / RROWS;
            int row = n - p * RROWS;
            ushort2 pr = gp[p];
            float* base = &tile[row * STRIDE];
            float xi = base[pr.x];
            float xj = base[pr.y];
            base[pr.x] = c * xi - s * xj;   // new col i of (M U^T)
            base[pr.y] = s * xi + c * xj;   // new col j
        }
        __syncthreads();
    }

    // transposed store: out[b, col, r0+row]  (consecutive lanes -> consecutive rows)
    float* dstb = out + (size_t)b * DD * DD + r0;
    for (int n = tid; n < DD * RROWS; n += THREADS) {
        int col = n / RROWS;
        int row = n - col * RROWS;
        dstb[(size_t)col * DD + row] = tile[row * STRIDE + col];
    }
}

__global__ __launch_bounds__(THREADS, 1)
void rbs_pass1(const float* __restrict__ in, const float* __restrict__ angles) {
    rbs_body(in, g_tmp, angles);
}

__global__ __launch_bounds__(THREADS, 1)
void rbs_pass2(float* __restrict__ out, const float* __restrict__ angles) {
    rbs_body(g_tmp, out, angles);
}

extern "C" void kernel_launch(void* const* d_in, const int* in_sizes, int n_in,
                              void* d_out, int out_size) {
    const float* input_state = (const float*)d_in[0];  // [64, 780, 780] f32
    const float* angles      = (const float*)d_in[1];  // [39] f32
    float* out = (float*)d_out;                        // [64, 780, 780] f32

    const size_t smem = (size_t)RROWS * STRIDE * sizeof(float);  // 203,060 B
    cudaFuncSetAttribute(rbs_pass1, cudaFuncAttributeMaxDynamicSharedMemorySize, (int)smem);
    cudaFuncSetAttribute(rbs_pass2, cudaFuncAttributeMaxDynamicSharedMemorySize, (int)smem);

    dim3 grid(NBATCH * NTILES);
    rbs_pass1<<<grid, THREADS, smem>>>(input_state, angles);
    rbs_pass2<<<grid, THREADS, smem>>>(out, angles);
}